// round 13
// baseline (speedup 1.0000x reference)
#include <cuda_runtime.h>
#include <cuda_fp16.h>
#include <math.h>

// ---------------------------------------------------------------------------
// ControllerLSTM on GB300, round 11.
// r10 showed: table architecture good (main 184us) but 68us of prelude and a
// latency-bound 8us/cell loop. This round:
//  (1) prelude fused into controller_main's prologue: each CTA converts its
//      own W_hh slice (20/32 ktiles -> 160KB smem cache, 12/32 -> private
//      global stream buffer) AND computes its own 112x64 table slice into
//      SMEM via mma (16 table warps + 16 convert warps concurrently).
//  (2) producer writes h as pre-packed hi/lo mma B-fragments (CTA k owns
//      exactly ktile k), so A-warps do barrier -> mma directly (no staging,
//      no split, no BARA); reduce+pointwise merged into one step.
// Only 2 kernel launches: build_eb (E fragments + flag reset), main.
// ---------------------------------------------------------------------------

#define H    2048
#define BSZ  1024
#define NBK  12

#define NCTA  128
#define NTHR  1024      // warps 0..15: A (mma) / table ; 16..31: B (decode) / convert

// E B-fragments for the table GEMM: [nt(14)][kt(128)][lane] uint2
__device__ uint2  g_eb[(size_t)14 * 128 * 32];
// per-CTA streamed W_hh fragments: [(cta*16 + awarp)*12 + ci][lane] uint4
__device__ uint4  g_wstream[(size_t)NCTA * 16 * 12 * 32];   // 12.6 MB
// packed h as mma B-operands: [buf][kt*8 + part*4 + cb] uint2 (part 0=hi,1=lo)
__device__ uint2  g_hpk[2 * 1024];
__device__ float  g_hbuf[2][H];
__device__ float  g_cbuf[H];

#define FLAG_STRIDE 8
__device__ volatile unsigned g_arrive[NCTA * FLAG_STRIDE];

__device__ __forceinline__ void grid_sync_flags(unsigned gen) {
    __syncthreads();
    if (threadIdx.x == 0) {
        __threadfence();
        g_arrive[blockIdx.x * FLAG_STRIDE] = gen;
    }
    if (threadIdx.x < NCTA) {
        while (g_arrive[threadIdx.x * FLAG_STRIDE] < gen) { }
    }
    __syncthreads();
}

__device__ __forceinline__ float wred(float v) {
    #pragma unroll
    for (int o = 16; o > 0; o >>= 1) v += __shfl_xor_sync(0xffffffffu, v, o);
    return v;
}

__device__ __forceinline__ float sigf(float x) { return 1.0f / (1.0f + expf(-x)); }

__device__ __forceinline__ unsigned pack2(float a, float b) {
    __half2 h = __floats2half2_rn(a, b);
    return *(unsigned*)&h;
}

__device__ __forceinline__ void mma16816(float* d, uint4 a, uint2 b) {
    asm volatile(
        "mma.sync.aligned.m16n8k16.row.col.f32.f16.f16.f32 "
        "{%0,%1,%2,%3}, {%4,%5,%6,%7}, {%8,%9}, {%0,%1,%2,%3};\n"
        : "+f"(d[0]), "+f"(d[1]), "+f"(d[2]), "+f"(d[3])
        : "r"(a.x), "r"(a.y), "r"(a.z), "r"(a.w), "r"(b.x), "r"(b.y));
}

#define BARB() asm volatile("bar.sync 1, 512;" ::: "memory")   // B warps

__device__ __forceinline__ void dec_params(int s, const float* dec_act,
                                           const float* dec_block,
                                           const float** dec, int* ncls) {
    if (s == 0) { *dec = dec_act; *ncls = 4; }
    else if (s & 1) { int bid = (s + 1) >> 1; *dec = dec_block + (size_t)(bid - 1) * (NBK - 1) * H; *ncls = bid; }
    else            { int bid = s >> 1;       *dec = dec_act   + (size_t)bid * 4 * H;               *ncls = 4; }
}

__device__ __forceinline__ const float* emb_row_ptr(int n, const float* enc_act,
                                                    const float* enc_block) {
    if (n < 44) return enc_act + (size_t)n * H;
    if (n < 110) {
        int r2 = n - 44;
        int bid = 1;
        while (bid * (bid + 1) / 2 <= r2) bid++;
        int j = r2 - bid * (bid - 1) / 2;
        return enc_block + (size_t)((bid - 1) * (NBK - 1) + j) * H;
    }
    return 0;
}

// ===========================================================================
// Kernel 0: build E B-fragments; zero barrier flags (replay safety).
// ===========================================================================
__global__ __launch_bounds__(256, 4)
void build_eb(const float* __restrict__ enc_act, const float* __restrict__ enc_block)
{
    if (blockIdx.x == 0) {
        for (int i = threadIdx.x; i < NCTA * FLAG_STRIDE; i += 256)
            g_arrive[i] = 0;
    }
    const int idx = blockIdx.x * 256 + threadIdx.x;      // 14*128*32 = 57344
    const int nt = idx >> 12;
    const int rem = idx & 4095;
    const int kt = rem >> 5;
    const int l  = rem & 31;
    const int n  = nt * 8 + (l >> 2);
    const int k  = kt * 16 + (l & 3) * 2;

    const float* p = emb_row_ptr(n, enc_act, enc_block);
    float f0 = 0.f, f1 = 0.f, f8 = 0.f, f9 = 0.f;
    if (p) { f0 = p[k]; f1 = p[k + 1]; f8 = p[k + 8]; f9 = p[k + 9]; }
    g_eb[idx] = make_uint2(pack2(f0, f1), pack2(f8, f9));
}

// ===========================================================================
// Kernel 1: persistent controller with fused prologue.
// dyn smem: [0,160K) wcache | [160K,+29120) T_sm (112 x 65 fp32) | h_smf 8K
// ===========================================================================
__global__ __launch_bounds__(NTHR, 1)
void controller_main(const float* __restrict__ W_ih,
                     const float* __restrict__ W_hh,
                     const float* __restrict__ b_ih,
                     const float* __restrict__ b_hh,
                     const float* __restrict__ dec_act,
                     const float* __restrict__ dec_block,
                     float* __restrict__ out)
{
    extern __shared__ unsigned char dynsm[];
    uint4* wcache = (uint4*)dynsm;                       // 16 warps * 20 kt * 32
    float* T_sm   = (float*)(dynsm + 163840);            // [112][65]
    float* h_smf  = (float*)(dynsm + 192960);            // 2048 fp32

    __shared__ unsigned tile[32][16][8];                 // conversion staging 16KB
    __shared__ float psum[4][4][16];
    __shared__ float h16_sm[16];
    __shared__ float c_sm[16];
    __shared__ float dec_sm[16];
    __shared__ int   row_sm;
    __shared__ int   idx_final;

    const int tid  = threadIdx.x;
    const int lane = tid & 31;
    const int wid  = tid >> 5;
    const int cta  = blockIdx.x;
    const bool grpA = (wid < 16);

    // per-gate biases, live in the 16 pointwise threads
    float bsum4[4] = {0.f, 0.f, 0.f, 0.f};
    if (tid < 16) {
        #pragma unroll
        for (int g = 0; g < 4; g++) {
            const int r = g * H + cta * 16 + tid;
            bsum4[g] = b_ih[r] + b_hh[r];
        }
    }

    // ---- zero T_sm ----
    for (int i = tid; i < 112 * 65; i += NTHR) T_sm[i] = 0.f;
    __syncthreads();

    // =======================================================================
    // PROLOGUE
    // =======================================================================
    if (grpA) {
        // ---- table warps: T_sm[n][g*16+j] = sum_k E[n][k]*W_ih[g*H+cta*16+j][k]
        const int g  = wid >> 2;
        const int s4 = wid & 3;
        const int row = lane & 15, half = lane >> 4;
        const int gr = lane >> 2, cb = lane & 3;
        #pragma unroll 1
        for (int pass = 0; pass < 2; pass++) {
            float d[7][4];
            #pragma unroll
            for (int a = 0; a < 7; a++)
                #pragma unroll
                for (int i = 0; i < 4; i++) d[a][i] = 0.f;
            for (int ci = 0; ci < 32; ci++) {
                const int kt = s4 * 32 + ci;
                const size_t rbase = (size_t)(g * H + cta * 16 + row) * H + kt * 16;
                #pragma unroll
                for (int p = 0; p < 2; p++) {
                    const int off = half * 4 + p * 8;
                    const float4 v = __ldg((const float4*)(W_ih + rbase + off));
                    tile[wid][row][(off >> 1) + 0] = pack2(v.x, v.y);
                    tile[wid][row][(off >> 1) + 1] = pack2(v.z, v.w);
                }
                __syncwarp();
                uint4 a0;
                a0.x = tile[wid][gr][cb];     a0.y = tile[wid][gr + 8][cb];
                a0.z = tile[wid][gr][cb + 4]; a0.w = tile[wid][gr + 8][cb + 4];
                __syncwarp();
                #pragma unroll
                for (int nt7 = 0; nt7 < 7; nt7++) {
                    const int nt = pass * 7 + nt7;
                    const uint2 b = g_eb[((size_t)nt * 128 + kt) * 32 + lane];
                    mma16816(d[nt7], a0, b);
                }
            }
            #pragma unroll
            for (int nt7 = 0; nt7 < 7; nt7++) {
                const int n0 = (pass * 7 + nt7) * 8;
                atomicAdd(&T_sm[(n0 + 2 * cb    ) * 65 + g * 16 + gr    ], d[nt7][0]);
                atomicAdd(&T_sm[(n0 + 2 * cb + 1) * 65 + g * 16 + gr    ], d[nt7][1]);
                atomicAdd(&T_sm[(n0 + 2 * cb    ) * 65 + g * 16 + gr + 8], d[nt7][2]);
                atomicAdd(&T_sm[(n0 + 2 * cb + 1) * 65 + g * 16 + gr + 8], d[nt7][3]);
            }
        }
    } else {
        // ---- convert warps: W_hh fragments for A-warp aw = wid-16 ----
        const int aw = wid - 16;
        const int g  = aw >> 2;
        const int s4 = aw & 3;
        const int row = lane & 15, half = lane >> 4;
        const int gr = lane >> 2, cb = lane & 3;
        for (int ci = 0; ci < 32; ci++) {
            const int kt = s4 * 32 + ci;
            const size_t rbase = (size_t)(g * H + cta * 16 + row) * H + kt * 16;
            #pragma unroll
            for (int p = 0; p < 2; p++) {
                const int off = half * 4 + p * 8;
                const float4 v = __ldg((const float4*)(W_hh + rbase + off));
                tile[wid][row][(off >> 1) + 0] = pack2(v.x, v.y);
                tile[wid][row][(off >> 1) + 1] = pack2(v.z, v.w);
            }
            __syncwarp();
            uint4 fr;
            fr.x = tile[wid][gr][cb];     fr.y = tile[wid][gr + 8][cb];
            fr.z = tile[wid][gr][cb + 4]; fr.w = tile[wid][gr + 8][cb + 4];
            __syncwarp();
            if (ci < 20) wcache[((size_t)aw * 20 + ci) * 32 + lane] = fr;
            else         g_wstream[(((size_t)cta * 16 + aw) * 12 + (ci - 20)) * 32 + lane] = fr;
        }
    }
    __syncthreads();

    // =======================================================================
    // CELL LOOP
    // =======================================================================
    const int gA = wid >> 2, s4A = wid & 3;
    const uint4* wcl = wcache + (size_t)wid * 20 * 32 + lane;
    const uint4* wst = g_wstream + ((size_t)cta * 16 + wid) * 12 * 32 + lane;

    unsigned gen = 0;

    for (int cell = 0; cell < 2 * NBK - 1; cell++) {
        if (cell > 0) {
            const int buf = (cell - 1) & 1;
            if (grpA) {
                // ---- A: mma immediately (b = packed h fragments from global) ----
                float d0[4] = {0.f, 0.f, 0.f, 0.f};
                float d1[4] = {0.f, 0.f, 0.f, 0.f};
                const bool bl = (lane < 8);
                #pragma unroll
                for (int c8 = 0; c8 < 4; c8++) {
                    uint2 breg[8];
                    #pragma unroll
                    for (int i = 0; i < 8; i++)
                        breg[i] = bl ? __ldcv(&g_hpk[buf * 1024 + (s4A * 32 + c8 * 8 + i) * 8 + lane])
                                     : make_uint2(0u, 0u);
                    #pragma unroll
                    for (int i = 0; i < 8; i++) {
                        const int ci = c8 * 8 + i;
                        const uint4 fa = (ci < 20) ? wcl[ci * 32] : wst[(ci - 20) * 32];
                        mma16816((i & 1) ? d1 : d0, fa, breg[i]);
                    }
                }
                if ((lane & 3) == 0) {
                    const int gr = lane >> 2;
                    psum[gA][s4A][gr]     = d0[0] + d0[1] + d1[0] + d1[1];
                    psum[gA][s4A][gr + 8] = d0[2] + d0[3] + d1[2] + d1[3];
                }
            } else {
                // ---- B: stage h, decode h_{cell-1}, argmax -> table row ----
                const int b = wid - 16;
                ((float4*)h_smf)[b * 32 + lane] =
                    __ldcv((const float4*)g_hbuf[buf] + b * 32 + lane);
                BARB();
                const float* dec; int ncls;
                dec_params(cell - 1, dec_act, dec_block, &dec, &ncls);
                if (b < ncls) {
                    const float4* dr = (const float4*)(dec + (size_t)b * H);
                    const float4* hp = (const float4*)h_smf;
                    float s = 0.f;
                    #pragma unroll 4
                    for (int t = lane; t < 512; t += 32) {
                        const float4 dv = __ldg(dr + t), hv = hp[t];
                        s += dv.x*hv.x + dv.y*hv.y + dv.z*hv.z + dv.w*hv.w;
                    }
                    s = wred(s);
                    if (lane == 0) dec_sm[b] = s;
                }
                BARB();
                if (wid == 16 && lane == 0) {
                    float best = dec_sm[0]; int bi = 0;
                    for (int j = 1; j < ncls; j++) { float v = dec_sm[j]; if (v > best) { best = v; bi = j; } }
                    const int bid = (cell + 1) >> 1;
                    row_sm = (cell & 1) ? ((bid - 1) * 4 + bi)
                                        : (44 + bid * (bid - 1) / 2 + bi);
                }
            }
            __syncthreads();   // join: psum + row_sm ready
        }

        // ---- pointwise + producer packing (16 threads) ----
        if (tid < 16) {
            float gate[4];
            if (cell == 0) {
                #pragma unroll
                for (int g = 0; g < 4; g++) gate[g] = bsum4[g];
            } else {
                const int rw = row_sm;
                #pragma unroll
                for (int g = 0; g < 4; g++) {
                    float s = bsum4[g] + T_sm[rw * 65 + g * 16 + tid];
                    #pragma unroll
                    for (int k = 0; k < 4; k++) s += psum[g][k][tid];
                    gate[g] = s;
                }
            }
            const float cprev = (cell == 0) ? 0.f : c_sm[tid];
            const float c2 = sigf(gate[1]) * cprev + sigf(gate[0]) * tanhf(gate[2]);
            const float h2 = sigf(gate[3]) * tanhf(c2);
            c_sm[tid] = c2;
            h16_sm[tid] = h2;
            const int buf = cell & 1;
            g_hbuf[buf][cta * 16 + tid] = h2;
            if (cell == 2 * NBK - 2) g_cbuf[cta * 16 + tid] = c2;
            __syncwarp(0x0000ffff);
            if (tid < 8) {
                const int cb = tid & 3, part = tid >> 2;
                const float f0 = h16_sm[2 * cb],     f1 = h16_sm[2 * cb + 1];
                const float f2 = h16_sm[8 + 2 * cb], f3 = h16_sm[9 + 2 * cb];
                uint2 u;
                if (part == 0) {
                    u = make_uint2(pack2(f0, f1), pack2(f2, f3));
                } else {
                    const float r0 = f0 - __half2float(__float2half_rn(f0));
                    const float r1 = f1 - __half2float(__float2half_rn(f1));
                    const float r2 = f2 - __half2float(__float2half_rn(f2));
                    const float r3 = f3 - __half2float(__float2half_rn(f3));
                    u = make_uint2(pack2(r0, r1), pack2(r2, r3));
                }
                g_hpk[buf * 1024 + cta * 8 + part * 4 + cb] = u;
            }
            __threadfence();
        }
        gen++;
        grid_sync_flags(gen);
    }

    // ---- epilogue: decode h_22 (buf 0) for the output idx ----
    if (tid < 512)
        ((float4*)h_smf)[tid] = __ldcv((const float4*)g_hbuf[0] + tid);
    __syncthreads();
    {
        const float* dec; int ncls;
        dec_params(2 * NBK - 2, dec_act, dec_block, &dec, &ncls);
        if (wid < ncls) {
            const float4* dr = (const float4*)(dec + (size_t)wid * H);
            const float4* hp = (const float4*)h_smf;
            float s = 0.f;
            #pragma unroll 4
            for (int t = lane; t < 512; t += 32) {
                const float4 dv = __ldg(dr + t), hv = hp[t];
                s += dv.x*hv.x + dv.y*hv.y + dv.z*hv.z + dv.w*hv.w;
            }
            s = wred(s);
            if (lane == 0) dec_sm[wid] = s;
        }
    }
    __syncthreads();
    if (tid == 0) {
        float best = dec_sm[0]; int bi = 0;
        for (int j = 1; j < 4; j++) { float v = dec_sm[j]; if (v > best) { best = v; bi = j; } }
        idx_final = bi;
    }
    // stage final c into the (now free) wcache region
    float4* cst = (float4*)dynsm;
    if (tid < 512) cst[tid] = __ldcv((const float4*)g_cbuf + tid);
    __syncthreads();

    // ---- replicate outputs to all 1024 (identical) batch rows ----
    if (cta == 0) {
        const float idxf = (float)idx_final;
        for (int i = tid; i < BSZ; i += NTHR) out[i] = idxf;
    }
    float4* outh = (float4*)(out + BSZ);
    float4* outc = (float4*)(out + BSZ + (size_t)BSZ * H);
    const float4* hfin = (const float4*)h_smf;
    for (int r = cta; r < BSZ; r += NCTA) {
        const size_t ro = (size_t)r * 512;
        for (int i = tid; i < 512; i += NTHR) {
            outh[ro + i] = hfin[i];
            outc[ro + i] = cst[i];
        }
    }
}

extern "C" void kernel_launch(void* const* d_in, const int* in_sizes, int n_in,
                              void* d_out, int out_size) {
    // metadata order: inputs, W_ih, W_hh, b_ih, b_hh, enc_act, enc_block, dec_act, dec_block
    const float* W_ih      = (const float*)d_in[1];
    const float* W_hh      = (const float*)d_in[2];
    const float* b_ih      = (const float*)d_in[3];
    const float* b_hh      = (const float*)d_in[4];
    const float* enc_act   = (const float*)d_in[5];
    const float* enc_block = (const float*)d_in[6];
    const float* dec_act   = (const float*)d_in[7];
    const float* dec_block = (const float*)d_in[8];
    float* out = (float*)d_out;

    const int main_smem = 201216;   // 160K wcache + 29120 T_sm + 8K h + pad
    cudaFuncSetAttribute(controller_main,
                         cudaFuncAttributeMaxDynamicSharedMemorySize, main_smem);

    build_eb<<<224, 256>>>(enc_act, enc_block);
    controller_main<<<NCTA, NTHR, main_smem>>>(W_ih, W_hh, b_ih, b_hh,
                                               dec_act, dec_block, out);
}

// round 14
// speedup vs baseline: 1.2367x; 1.2367x over previous
#include <cuda_runtime.h>
#include <cuda_fp16.h>
#include <math.h>

// ---------------------------------------------------------------------------
// ControllerLSTM on GB300, round 12.
// Base = round 10 (table + tensor-core main loop, 252.6us total, main 184us).
// r11's fused prologue regressed (bad streaming) and is reverted.
// Deltas vs r10:
//  (1) build_eb + flag-zero merged into convert_whh (3 launches total),
//  (2) decode reads dec/h straight from L2 (no h staging, one fewer BARB),
//  (3) mma rebalanced: A warps 24 smem ktiles; B warps do the 8 global
//      ktiles after decode (xB handoff via bar.arrive/bar.sync),
//  (4) redundant per-thread threadfence removed (barrier fence suffices).
// ---------------------------------------------------------------------------

#define H    2048
#define BSZ  1024
#define NBK  12

#define NCTA  128
#define NTHR  1024          // A warps: wid 0..15 (mma). B warps: wid 16..31.

// W_hh mma A-fragments: [cta*4+g][kt(128)][lane] uint4
__device__ uint4  g_whm[(size_t)NCTA * 4 * 128 * 32];   // 33.5 MB
// gate table: T[row(112)][g*2048 + col]  fp32
__device__ float  g_tab[(size_t)112 * 8192];            // 3.7 MB
// E B-fragments for the table GEMM: [nt(14)][kt(128)][lane] uint2
__device__ uint2  g_eb[(size_t)14 * 128 * 32];          // 459 KB
__device__ float  g_hbuf[2][H];
__device__ float  g_cbuf[H];

#define FLAG_STRIDE 8
__device__ volatile unsigned g_arrive[NCTA * FLAG_STRIDE];

// one-hop barrier; flags zeroed by convert_whh each launch (replay-safe)
__device__ __forceinline__ void grid_sync_flags(unsigned gen) {
    __syncthreads();
    if (threadIdx.x == 0) {
        __threadfence();
        g_arrive[blockIdx.x * FLAG_STRIDE] = gen;
    }
    if (threadIdx.x < NCTA) {
        while (g_arrive[threadIdx.x * FLAG_STRIDE] < gen) { }
    }
    __syncthreads();
}

__device__ __forceinline__ float wred(float v) {
    #pragma unroll
    for (int o = 16; o > 0; o >>= 1) v += __shfl_xor_sync(0xffffffffu, v, o);
    return v;
}

__device__ __forceinline__ float sigf(float x) { return 1.0f / (1.0f + expf(-x)); }

__device__ __forceinline__ unsigned pack2(float a, float b) {
    __half2 h = __floats2half2_rn(a, b);
    return *(unsigned*)&h;
}

__device__ __forceinline__ void split2(float f0, float f1, unsigned& hi, unsigned& lo) {
    const __half h0 = __float2half_rn(f0), h1 = __float2half_rn(f1);
    const __half2 hh = __halves2half2(h0, h1);
    hi = *(const unsigned*)&hh;
    const __half l0 = __float2half_rn(f0 - __half2float(h0));
    const __half l1 = __float2half_rn(f1 - __half2float(h1));
    const __half2 ll = __halves2half2(l0, l1);
    lo = *(const unsigned*)&ll;
}

__device__ __forceinline__ void mma16816(float* d, uint4 a, uint2 b) {
    asm volatile(
        "mma.sync.aligned.m16n8k16.row.col.f32.f16.f16.f32 "
        "{%0,%1,%2,%3}, {%4,%5,%6,%7}, {%8,%9}, {%0,%1,%2,%3};\n"
        : "+f"(d[0]), "+f"(d[1]), "+f"(d[2]), "+f"(d[3])
        : "r"(a.x), "r"(a.y), "r"(a.z), "r"(a.w), "r"(b.x), "r"(b.y));
}

#define BARB()        asm volatile("bar.sync 1, 512;"    ::: "memory")  // B warps
#define BARA()        asm volatile("bar.sync 2, 512;"    ::: "memory")  // A warps
#define BAR3_ARRIVE() asm volatile("bar.arrive 3, 1024;" ::: "memory")  // A -> B
#define BAR3_SYNC()   asm volatile("bar.sync 3, 1024;"   ::: "memory")  // B waits

__device__ __forceinline__ void dec_params(int s, const float* dec_act,
                                           const float* dec_block,
                                           const float** dec, int* ncls) {
    if (s == 0) { *dec = dec_act; *ncls = 4; }
    else if (s & 1) { int bid = (s + 1) >> 1; *dec = dec_block + (size_t)(bid - 1) * (NBK - 1) * H; *ncls = bid; }
    else            { int bid = s >> 1;       *dec = dec_act   + (size_t)bid * 4 * H;               *ncls = 4; }
}

__device__ __forceinline__ const float* emb_row_ptr(int n, const float* enc_act,
                                                    const float* enc_block) {
    if (n < 44) return enc_act + (size_t)n * H;
    if (n < 110) {
        int r2 = n - 44;
        int bid = 1;
        while (bid * (bid + 1) / 2 <= r2) bid++;
        int j = r2 - bid * (bid - 1) / 2;
        return enc_block + (size_t)((bid - 1) * (NBK - 1) + j) * H;
    }
    return 0;
}

// ===========================================================================
// Kernel 0: W_hh -> mma A-fragments; also builds E B-fragments (first 224
// blocks) and zeroes barrier flags (block 0).
// ===========================================================================
__global__ __launch_bounds__(256, 2)
void convert_whh(const float* __restrict__ W_hh,
                 const float* __restrict__ enc_act,
                 const float* __restrict__ enc_block)
{
    __shared__ unsigned tile[8][16][8];

    if (blockIdx.x == 0) {
        for (int i = threadIdx.x; i < NCTA * FLAG_STRIDE; i += 256)
            g_arrive[i] = 0;
    }
    // E fragment build (57344 entries across first 224 blocks)
    if (blockIdx.x < 224) {
        const int idx = blockIdx.x * 256 + threadIdx.x;
        const int nt = idx >> 12;
        const int rem = idx & 4095;
        const int kt = rem >> 5;
        const int l  = rem & 31;
        const int n  = nt * 8 + (l >> 2);
        const int k  = kt * 16 + (l & 3) * 2;
        const float* p = emb_row_ptr(n, enc_act, enc_block);
        float f0 = 0.f, f1 = 0.f, f8 = 0.f, f9 = 0.f;
        if (p) { f0 = p[k]; f1 = p[k + 1]; f8 = p[k + 8]; f9 = p[k + 9]; }
        g_eb[idx] = make_uint2(pack2(f0, f1), pack2(f8, f9));
    }

    const int wid  = threadIdx.x >> 5;
    const int lane = threadIdx.x & 31;
    const int T    = blockIdx.x * 8 + wid;        // 65536 tiles
    const int kt   = T & 127;
    const int gc   = T >> 7;                      // cta*4 + g
    const int g    = gc & 3;
    const int cta  = gc >> 2;

    const int row  = lane & 15;
    const int half = lane >> 4;
    const size_t rbase = (size_t)(g * H + cta * 16 + row) * H + kt * 16;

    #pragma unroll
    for (int p = 0; p < 2; p++) {
        const int off = half * 4 + p * 8;
        const float4 v = *(const float4*)(W_hh + rbase + off);
        tile[wid][row][(off >> 1) + 0] = pack2(v.x, v.y);
        tile[wid][row][(off >> 1) + 1] = pack2(v.z, v.w);
    }
    __syncwarp();

    const int gr = lane >> 2, c = lane & 3;
    uint4 frag;
    frag.x = tile[wid][gr    ][c    ];
    frag.y = tile[wid][gr + 8][c    ];
    frag.z = tile[wid][gr    ][c + 4];
    frag.w = tile[wid][gr + 8][c + 4];
    g_whm[(size_t)T * 32 + lane] = frag;
}

// ===========================================================================
// Kernel 1: table GEMM. T[n][m] = sum_k E[n][k] * W_ih[m][k].  (r10 verbatim)
// ===========================================================================
__global__ __launch_bounds__(256, 1)
void table_gemm(const float* __restrict__ W_ih)
{
    extern __shared__ float psum2[];                 // [8][14][16][8]
    __shared__ unsigned tile[8][2][16][8];

    const int tid  = threadIdx.x;
    const int w    = tid >> 5;
    const int lane = tid & 31;
    const int m0   = blockIdx.x * 32;
    const int gr   = lane >> 2, cb = lane & 3;

    float d[2][14][4];
    #pragma unroll
    for (int m = 0; m < 2; m++)
        #pragma unroll
        for (int nt = 0; nt < 14; nt++)
            #pragma unroll
            for (int i = 0; i < 4; i++) d[m][nt][i] = 0.f;

    for (int kt16 = 0; kt16 < 16; kt16++) {
        const int kt = w * 16 + kt16;
        const int row = lane & 15, half = lane >> 4;
        #pragma unroll
        for (int m = 0; m < 2; m++) {
            const size_t rbase = (size_t)(m0 + m * 16 + row) * H + kt * 16;
            #pragma unroll
            for (int p = 0; p < 2; p++) {
                const int off = half * 4 + p * 8;
                const float4 v = *(const float4*)(W_ih + rbase + off);
                tile[w][m][row][(off >> 1) + 0] = pack2(v.x, v.y);
                tile[w][m][row][(off >> 1) + 1] = pack2(v.z, v.w);
            }
        }
        __syncwarp();
        uint4 a0, a1;
        a0.x = tile[w][0][gr][cb];     a0.y = tile[w][0][gr + 8][cb];
        a0.z = tile[w][0][gr][cb + 4]; a0.w = tile[w][0][gr + 8][cb + 4];
        a1.x = tile[w][1][gr][cb];     a1.y = tile[w][1][gr + 8][cb];
        a1.z = tile[w][1][gr][cb + 4]; a1.w = tile[w][1][gr + 8][cb + 4];
        __syncwarp();
        #pragma unroll
        for (int nt = 0; nt < 14; nt++) {
            const uint2 b = g_eb[((size_t)nt * 128 + kt) * 32 + lane];
            mma16816(d[0][nt], a0, b);
            mma16816(d[1][nt], a1, b);
        }
    }

    #pragma unroll
    for (int m = 0; m < 2; m++) {
        #pragma unroll
        for (int nt = 0; nt < 14; nt++) {
            float* p = psum2 + ((size_t)(w * 14 + nt) * 16) * 8;
            p[gr * 8 + 2 * cb]           = d[m][nt][0];
            p[gr * 8 + 2 * cb + 1]       = d[m][nt][1];
            p[(gr + 8) * 8 + 2 * cb]     = d[m][nt][2];
            p[(gr + 8) * 8 + 2 * cb + 1] = d[m][nt][3];
        }
        __syncthreads();
        for (int i = tid; i < 14 * 128; i += 256) {
            const int nt = i >> 7, rem = i & 127;
            const int row = rem >> 3, col = rem & 7;
            float s = 0.f;
            #pragma unroll
            for (int w8 = 0; w8 < 8; w8++)
                s += psum2[(((size_t)(w8 * 14 + nt)) * 16 + row) * 8 + col];
            g_tab[(size_t)(nt * 8 + col) * 8192 + m0 + m * 16 + row] = s;
        }
        __syncthreads();
    }
}

// ===========================================================================
// Kernel 2: persistent controller.
// dyn smem: [0,192K) wcache | 192K xBhi 4K | 196.5K xBlo 4K | h_smf 8K.
// ===========================================================================
__global__ __launch_bounds__(NTHR, 1)
void controller_main(const float* __restrict__ b_ih,
                     const float* __restrict__ b_hh,
                     const float* __restrict__ dec_act,
                     const float* __restrict__ dec_block,
                     float* __restrict__ out)
{
    extern __shared__ unsigned char dynsm[];
    uint4* wcache = (uint4*)dynsm;                          // 12288 uint4
    uint2* xBhi   = (uint2*)(dynsm + 196608);               // 512
    uint2* xBlo   = (uint2*)(dynsm + 200704);               // 512
    float* h_smf  = (float*)(dynsm + 204800);               // 2048 fp32

    __shared__ float psum[4][8][16];
    __shared__ float tab_sm[64];
    __shared__ float dec_sm[16];
    __shared__ float c_sm[16];
    __shared__ int   idx_final;

    const int tid  = threadIdx.x;
    const int lane = tid & 31;
    const int wid  = tid >> 5;
    const int cta  = blockIdx.x;
    const bool grpA = (wid < 16);

    // biases live in the 16 pointwise threads
    float bsum4[4] = {0.f, 0.f, 0.f, 0.f};
    if (tid < 16) {
        #pragma unroll
        for (int g = 0; g < 4; g++) {
            const int r = g * H + cta * 16 + tid;
            bsum4[g] = b_ih[r] + b_hh[r];
        }
    }

    // A-warp geometry
    const int gA  = wid >> 2;
    const int s4A = wid & 3;
    const int ktbase = s4A * 32;
    const uint4* wcl = wcache + (size_t)wid * 24 * 32 + lane;

    // B-warp geometry
    const int bW  = wid - 16;                  // 0..15
    const int gB  = bW >> 2, s4B = bW & 3;
    const uint4* wgpB = g_whm + ((size_t)(cta * 4 + gB) * 128 + s4B * 32) * 32 + lane;

    // ---- fill 192 KB fragment cache: warp region covers ktiles [s4*32, +24) ----
    for (int s = tid; s < 16 * 24 * 32; s += NTHR) {
        const int l = s & 31, u = s >> 5;
        const int warpi = u / 24, ci = u - warpi * 24;
        const int g = warpi >> 2, sl = warpi & 3;
        wcache[s] = g_whm[((size_t)(cta * 4 + g) * 128 + sl * 32 + ci) * 32 + l];
    }
    __syncthreads();

    unsigned gen = 0;

    for (int cell = 0; cell < 2 * NBK - 1; cell++) {
        if (cell > 0) {
            const int buf = (cell - 1) & 1;
            const float* hb = g_hbuf[buf];

            if (grpA) {
                // ---- A: build xB (hi/lo), BARA, arrive, 24 smem mma ----
                {
                    const int slot = tid;                 // [0,512)
                    const int base = (slot >> 2) * 16 + 2 * (slot & 3);
                    const float2 p0 = __ldcv((const float2*)(hb + base));
                    const float2 p1 = __ldcv((const float2*)(hb + base + 8));
                    unsigned hx, lx, hy, ly;
                    split2(p0.x, p0.y, hx, lx);
                    split2(p1.x, p1.y, hy, ly);
                    xBhi[slot] = make_uint2(hx, hy);
                    xBlo[slot] = make_uint2(lx, ly);
                }
                BARA();
                BAR3_ARRIVE();
                float d0[4] = {0.f, 0.f, 0.f, 0.f};
                float d1[4] = {0.f, 0.f, 0.f, 0.f};
                const bool bl = (lane < 8);
                const uint2* xsrc = (lane < 4) ? xBhi : xBlo;
                const int cb = lane & 3;
                const uint2 bz = make_uint2(0u, 0u);
                #pragma unroll
                for (int ci = 0; ci < 24; ci += 2) {
                    const uint4 fa = wcl[ci * 32];
                    const uint4 fb = wcl[(ci + 1) * 32];
                    const uint2 ba  = bl ? xsrc[(ktbase + ci) * 4 + cb] : bz;
                    const uint2 bbv = bl ? xsrc[(ktbase + ci + 1) * 4 + cb] : bz;
                    mma16816(d0, fa, ba);
                    mma16816(d1, fb, bbv);
                }
                if ((lane & 3) == 0) {
                    const int gr = lane >> 2;
                    psum[gA][s4A][gr]     = d0[0] + d0[1] + d1[0] + d1[1];
                    psum[gA][s4A][gr + 8] = d0[2] + d0[3] + d1[2] + d1[3];
                }
            } else {
                // ---- B: decode directly from L2, argmax, table fetch, 8 mma ----
                const float* dec; int ncls;
                dec_params(cell - 1, dec_act, dec_block, &dec, &ncls);
                if (bW < ncls) {
                    const float4* dr = (const float4*)(dec + (size_t)bW * H);
                    const float4* hp = (const float4*)hb;
                    float s = 0.f;
                    #pragma unroll 4
                    for (int t = lane; t < 512; t += 32) {
                        const float4 dv = __ldg(dr + t);
                        const float4 hv = __ldcv(hp + t);
                        s += dv.x*hv.x + dv.y*hv.y + dv.z*hv.z + dv.w*hv.w;
                    }
                    s = wred(s);
                    if (lane == 0) dec_sm[bW] = s;
                }
                BARB();
                float best = dec_sm[0]; int bi = 0;
                for (int j = 1; j < ncls; j++) { float v = dec_sm[j]; if (v > best) { best = v; bi = j; } }
                const int bid = (cell + 1) >> 1;
                const int rowT = (cell & 1) ? ((bid - 1) * 4 + bi)
                                            : (44 + bid * (bid - 1) / 2 + bi);
                if (bW < 2) {
                    const int t = bW * 32 + lane;
                    if (t < 64)
                        tab_sm[t] = __ldg(g_tab + (size_t)rowT * 8192 +
                                          (t >> 4) * H + cta * 16 + (t & 15));
                }
                BAR3_SYNC();          // wait for xB from A warps
                float d0[4] = {0.f, 0.f, 0.f, 0.f};
                float d1[4] = {0.f, 0.f, 0.f, 0.f};
                const bool bl = (lane < 8);
                const uint2* xsrc = (lane < 4) ? xBhi : xBlo;
                const int cb = lane & 3;
                const uint2 bz = make_uint2(0u, 0u);
                const int ktb = s4B * 32;
                #pragma unroll
                for (int kl = 24; kl < 32; kl += 2) {
                    const uint4 fa = wgpB[kl * 32];
                    const uint4 fb = wgpB[(kl + 1) * 32];
                    const uint2 ba  = bl ? xsrc[(ktb + kl) * 4 + cb] : bz;
                    const uint2 bbv = bl ? xsrc[(ktb + kl + 1) * 4 + cb] : bz;
                    mma16816(d0, fa, ba);
                    mma16816(d1, fb, bbv);
                }
                if ((lane & 3) == 0) {
                    const int gr = lane >> 2;
                    psum[gB][4 + s4B][gr]     = d0[0] + d0[1] + d1[0] + d1[1];
                    psum[gB][4 + s4B][gr + 8] = d0[2] + d0[3] + d1[2] + d1[3];
                }
            }
            __syncthreads();   // join: psum + tab_sm ready
        }

        // ---- pointwise (16 threads) ----
        if (tid < 16) {
            float gate[4];
            if (cell == 0) {
                #pragma unroll
                for (int g = 0; g < 4; g++) gate[g] = bsum4[g];
            } else {
                #pragma unroll
                for (int g = 0; g < 4; g++) {
                    float s = bsum4[g] + tab_sm[g * 16 + tid];
                    #pragma unroll
                    for (int k = 0; k < 8; k++) s += psum[g][k][tid];
                    gate[g] = s;
                }
            }
            const float cprev = (cell == 0) ? 0.f : c_sm[tid];
            const float c2 = sigf(gate[1]) * cprev + sigf(gate[0]) * tanhf(gate[2]);
            const float h2 = sigf(gate[3]) * tanhf(c2);
            c_sm[tid] = c2;
            g_hbuf[cell & 1][cta * 16 + tid] = h2;
            if (cell == 2 * NBK - 2) g_cbuf[cta * 16 + tid] = c2;
        }
        gen++;
        grid_sync_flags(gen);
    }

    // ---- epilogue: decode h_22 (buf 0) for the output idx ----
    if (tid < 512)
        ((float4*)h_smf)[tid] = __ldcv((const float4*)g_hbuf[0] + tid);
    __syncthreads();
    {
        const float* dec; int ncls;
        dec_params(2 * NBK - 2, dec_act, dec_block, &dec, &ncls);
        if (wid < ncls) {
            const float4* dr = (const float4*)(dec + (size_t)wid * H);
            const float4* hp = (const float4*)h_smf;
            float s = 0.f;
            #pragma unroll 4
            for (int t = lane; t < 512; t += 32) {
                const float4 dv = __ldg(dr + t), hv = hp[t];
                s += dv.x*hv.x + dv.y*hv.y + dv.z*hv.z + dv.w*hv.w;
            }
            s = wred(s);
            if (lane == 0) dec_sm[wid] = s;
        }
    }
    __syncthreads();
    if (tid == 0) {
        float best = dec_sm[0]; int bi = 0;
        for (int j = 1; j < 4; j++) { float v = dec_sm[j]; if (v > best) { best = v; bi = j; } }
        idx_final = bi;
    }
    // stage final c into the (now free) wcache region
    float4* cst = (float4*)dynsm;
    if (tid < 512) cst[tid] = __ldcv((const float4*)g_cbuf + tid);
    __syncthreads();

    // ---- replicate outputs to all 1024 (identical) batch rows ----
    if (cta == 0) {
        const float idxf = (float)idx_final;
        for (int i = tid; i < BSZ; i += NTHR) out[i] = idxf;
    }
    float4* outh = (float4*)(out + BSZ);
    float4* outc = (float4*)(out + BSZ + (size_t)BSZ * H);
    const float4* hfin = (const float4*)h_smf;
    for (int r = cta; r < BSZ; r += NCTA) {
        const size_t ro = (size_t)r * 512;
        for (int i = tid; i < 512; i += NTHR) {
            outh[ro + i] = hfin[i];
            outc[ro + i] = cst[i];
        }
    }
}

extern "C" void kernel_launch(void* const* d_in, const int* in_sizes, int n_in,
                              void* d_out, int out_size) {
    // metadata order: inputs, W_ih, W_hh, b_ih, b_hh, enc_act, enc_block, dec_act, dec_block
    const float* W_ih      = (const float*)d_in[1];
    const float* W_hh      = (const float*)d_in[2];
    const float* b_ih      = (const float*)d_in[3];
    const float* b_hh      = (const float*)d_in[4];
    const float* enc_act   = (const float*)d_in[5];
    const float* enc_block = (const float*)d_in[6];
    const float* dec_act   = (const float*)d_in[7];
    const float* dec_block = (const float*)d_in[8];
    float* out = (float*)d_out;

    const int main_smem = 212992;   // 192K cache + 4K + 4K + 8K
    cudaFuncSetAttribute(controller_main,
                         cudaFuncAttributeMaxDynamicSharedMemorySize, main_smem);
    const int gemm_smem = 8 * 14 * 16 * 8 * sizeof(float);   // 57344
    cudaFuncSetAttribute(table_gemm,
                         cudaFuncAttributeMaxDynamicSharedMemorySize, gemm_smem);

    convert_whh<<<8192, 256>>>(W_hh, enc_act, enc_block);
    table_gemm<<<256, 256, gemm_smem>>>(W_ih);
    controller_main<<<NCTA, NTHR, main_smem>>>(b_ih, b_hh, dec_act, dec_block, out);
}